// round 9
// baseline (speedup 1.0000x reference)
#include <cuda_runtime.h>
#include <cuda_bf16.h>
#include <cstdint>

#define BATCH   2048
#define LATD    32
#define HID     256
#define DIM     20
#define TST     512

#define ROWS    32                 // batch rows per CLUSTER
#define CLUSTER 2
#define NCTA    ((BATCH / ROWS) * CLUSTER)   // 128
#define NT      512                // 16 warps per CTA: (colw 0..7) x (mt 0..1)
#define NSLOT   16                 // global column-owner slots (2 CTAs x 8)

#define KS0     18                 // layer0: cols 0..287  (x|1|0|h0)
#define KS1     33                 // layer1: cols 16..543 (..|1|..|h0|h1)
#define AS      552                // u16 elements per activation row
#define ROWB    (AS * 2)           // bytes per row
#define MTOFF   (16 * ROWB)        // m-tile 1 byte offset
#define H0C     32
#define H1C     288

#define SMEM_BYTES (32*AS*2*2 + 8*32*33*4 + ROWS*LATD*4)   // 108544

// ---------------- fragment-major packed weights (repacked each launch) ----------------
__device__ uint4 g_W0[NSLOT * KS0 * 8 * 32];
__device__ uint4 g_W1[NSLOT * KS1 * 8 * 32];
__device__ uint4 g_PJ[8 * 2 * 4 * 32];

// ---------------- helpers ----------------
__device__ __forceinline__ float sigm(float x) {
    return __fdividef(1.f, 1.f + __expf(-x));
}
__device__ __forceinline__ float tanh_(float x) {
    float e = __expf(2.f * x);
    return 1.f - __fdividef(2.f, e + 1.f);
}
__device__ __forceinline__ void split2(float x, unsigned short& hi, unsigned short& lo) {
    __nv_bfloat16 h = __float2bfloat16_rn(x);
    hi = __bfloat16_as_ushort(h);
    lo = __bfloat16_as_ushort(__float2bfloat16_rn(x - __bfloat162float(h)));
}
__device__ __forceinline__ uint32_t smem_u32(const void* p) {
    uint32_t a;
    asm("{ .reg .u64 t; cvta.to.shared.u64 t, %1; cvt.u32.u64 %0, t; }" : "=r"(a) : "l"(p));
    return a;
}
__device__ __forceinline__ uint32_t mapa_sh(uint32_t addr, uint32_t rank) {
    uint32_t r;
    asm("mapa.shared::cluster.u32 %0, %1, %2;" : "=r"(r) : "r"(addr), "r"(rank));
    return r;
}
__device__ __forceinline__ void st_remote_u32(uint32_t addr, uint32_t v) {
    asm volatile("st.shared::cluster.u32 [%0], %1;" :: "r"(addr), "r"(v) : "memory");
}
__device__ __forceinline__ void cluster_sync_() {
    asm volatile("barrier.cluster.arrive.aligned;" ::: "memory");
    asm volatile("barrier.cluster.wait.aligned;" ::: "memory");
}
__device__ __forceinline__ void ldsm4(uint32_t& r0, uint32_t& r1, uint32_t& r2, uint32_t& r3,
                                      uint32_t a) {
    asm volatile("ldmatrix.sync.aligned.m8n8.x4.shared.b16 {%0,%1,%2,%3}, [%4];"
                 : "=r"(r0), "=r"(r1), "=r"(r2), "=r"(r3) : "r"(a));
}
__device__ __forceinline__ void mma16816(float* c, uint32_t a0, uint32_t a1, uint32_t a2,
                                         uint32_t a3, uint32_t b0, uint32_t b1) {
    asm volatile(
        "mma.sync.aligned.m16n8k16.row.col.f32.bf16.bf16.f32 "
        "{%0,%1,%2,%3}, {%4,%5,%6,%7}, {%8,%9}, {%0,%1,%2,%3};"
        : "+f"(c[0]), "+f"(c[1]), "+f"(c[2]), "+f"(c[3])
        : "r"(a0), "r"(a1), "r"(a2), "r"(a3), "r"(b0), "r"(b1));
}

// ---------------- repack: weight element accessors (kc = activation column) ----------------
__device__ __forceinline__ float W0val(int kc, int n,
                                       const float* w_ih0, const float* w_hh0,
                                       const float* b_ih0, const float* b_hh0) {
    int u = n >> 2, g = n & 3, row = g * HID + u;
    if (kc < DIM)  return w_ih0[row * DIM + kc];
    if (kc == 20)  return b_ih0[row] + b_hh0[row];
    if (kc < 32)   return 0.f;
    return w_hh0[row * HID + (kc - 32)];
}
__device__ __forceinline__ float W1val(int kc, int n,
                                       const float* w_ih1, const float* w_hh1,
                                       const float* b_ih1, const float* b_hh1) {
    int u = n >> 2, g = n & 3, row = g * HID + u;
    if (kc == 20)  return b_ih1[row] + b_hh1[row];
    if (kc >= 288) return w_hh1[row * HID + (kc - 288)];
    if (kc >= 32)  return w_ih1[row * HID + (kc - 32)];
    return 0.f;
}
__device__ __forceinline__ uint4 pack_frag(float e00, float e01, float e10, float e11) {
    unsigned short h00, l00, h01, l01, h10, l10, h11, l11;
    split2(e00, h00, l00); split2(e01, h01, l01);
    split2(e10, h10, l10); split2(e11, h11, l11);
    uint4 v;
    v.x = (uint32_t)h00 | ((uint32_t)h01 << 16);
    v.y = (uint32_t)h10 | ((uint32_t)h11 << 16);
    v.z = (uint32_t)l00 | ((uint32_t)l01 << 16);
    v.w = (uint32_t)l10 | ((uint32_t)l11 << 16);
    return v;
}

__global__ void repack_kernel(const float* __restrict__ w_ih0, const float* __restrict__ w_hh0,
                              const float* __restrict__ b_ih0, const float* __restrict__ b_hh0,
                              const float* __restrict__ w_ih1, const float* __restrict__ w_hh1,
                              const float* __restrict__ b_ih1, const float* __restrict__ b_hh1,
                              const float* __restrict__ w_proj) {
    const int stride = gridDim.x * blockDim.x;
    const int base   = blockIdx.x * blockDim.x + threadIdx.x;

    const int N0 = NSLOT * KS0 * 8 * 32;
    for (int idx = base; idx < N0; idx += stride) {
        int lane = idx & 31, t = idx >> 5;
        int nt = t & 7; t >>= 3;
        int ks = t % KS0, w = t / KS0;
        int n  = w * 64 + nt * 8 + (lane >> 2);
        int kc = ks * 16 + (lane & 3) * 2;
        g_W0[idx] = pack_frag(W0val(kc,     n, w_ih0, w_hh0, b_ih0, b_hh0),
                              W0val(kc + 1, n, w_ih0, w_hh0, b_ih0, b_hh0),
                              W0val(kc + 8, n, w_ih0, w_hh0, b_ih0, b_hh0),
                              W0val(kc + 9, n, w_ih0, w_hh0, b_ih0, b_hh0));
    }
    const int N1 = NSLOT * KS1 * 8 * 32;
    for (int idx = base; idx < N1; idx += stride) {
        int lane = idx & 31, t = idx >> 5;
        int nt = t & 7; t >>= 3;
        int ks = t % KS1, w = t / KS1;
        int n  = w * 64 + nt * 8 + (lane >> 2);
        int kc = 16 + ks * 16 + (lane & 3) * 2;
        g_W1[idx] = pack_frag(W1val(kc,     n, w_ih1, w_hh1, b_ih1, b_hh1),
                              W1val(kc + 1, n, w_ih1, w_hh1, b_ih1, b_hh1),
                              W1val(kc + 8, n, w_ih1, w_hh1, b_ih1, b_hh1),
                              W1val(kc + 9, n, w_ih1, w_hh1, b_ih1, b_hh1));
    }
    const int NP = 8 * 2 * 4 * 32;
    for (int idx = base; idx < NP; idx += stride) {
        int lane = idx & 31, t = idx >> 5;
        int nt = t & 3; t >>= 2;
        int ks = t & 1, w = t >> 1;
        int n  = nt * 8 + (lane >> 2);
        int kc = w * 32 + ks * 16 + (lane & 3) * 2;
        float e00 = (n < DIM) ? w_proj[n * HID + kc]     : 0.f;
        float e01 = (n < DIM) ? w_proj[n * HID + kc + 1] : 0.f;
        float e10 = (n < DIM) ? w_proj[n * HID + kc + 8] : 0.f;
        float e11 = (n < DIM) ? w_proj[n * HID + kc + 9] : 0.f;
        g_PJ[idx] = pack_frag(e00, e01, e10, e11);
    }
}

// ---------------- 3-pass bf16-split MMA over one m-tile, 4 n-tiles, B prefetch ----------------
template <int KSTEPS, int KSTRIDE>
__device__ __forceinline__ void mma_tile(uint32_t aHi, uint32_t aLo,
                                         const uint4* __restrict__ wf,
                                         float (&acc)[4][4]) {
    #pragma unroll
    for (int n = 0; n < 4; ++n)
        #pragma unroll
        for (int i = 0; i < 4; ++i) acc[n][i] = 0.f;

    uint4 B[4];
    #pragma unroll
    for (int n = 0; n < 4; ++n) B[n] = __ldg(wf + n * 32);

    #pragma unroll 2
    for (int ks = 0; ks < KSTEPS; ++ks) {
        uint4 Bn[4];
        if (ks + 1 < KSTEPS) {
            #pragma unroll
            for (int n = 0; n < 4; ++n)
                Bn[n] = __ldg(wf + (size_t)(ks + 1) * KSTRIDE + n * 32);
        }
        uint32_t h0, h1, h2, h3, l0, l1, l2, l3;
        ldsm4(h0, h1, h2, h3, aHi + ks * 32);
        ldsm4(l0, l1, l2, l3, aLo + ks * 32);
        #pragma unroll
        for (int n = 0; n < 4; ++n) {
            mma16816(acc[n], h0, h1, h2, h3, B[n].x, B[n].y);   // hiA*hiB
            mma16816(acc[n], l0, l1, l2, l3, B[n].x, B[n].y);   // loA*hiB
            mma16816(acc[n], h0, h1, h2, h3, B[n].z, B[n].w);   // hiA*loB
        }
        #pragma unroll
        for (int n = 0; n < 4; ++n) B[n] = Bn[n];
    }
}

// ---------------- LSTM epilogue for 4 n-tiles of one half ----------------
__device__ __forceinline__ void lstm_epi(float (&acc)[4][4], int half, int odd,
                                         float (&cs)[8], uint32_t (&hp)[8]) {
    #pragma unroll
    for (int n = 0; n < 4; ++n) {
        float a0 = acc[n][0], a1 = acc[n][1];
        float a2 = acc[n][2], a3 = acc[n][3];
        float t0 = __shfl_xor_sync(0xffffffffu, a0, 1);
        float t1 = __shfl_xor_sync(0xffffffffu, a1, 1);
        float t2 = __shfl_xor_sync(0xffffffffu, a2, 1);
        float t3 = __shfl_xor_sync(0xffffffffu, a3, 1);
        float gi = odd ? t2 : a0;
        float gf = odd ? t3 : a1;
        float gg = odd ? a2 : t0;
        float go = odd ? a3 : t1;
        int idx = half * 4 + n;
        float c = sigm(gf) * cs[idx] + sigm(gi) * tanh_(gg);
        cs[idx] = c;
        float h = sigm(go) * tanh_(c);
        unsigned short hh, hl;
        split2(h, hh, hl);
        hp[idx] = (uint32_t)hh | ((uint32_t)hl << 16);
    }
}

// ---------------- main persistent clustered kernel ----------------
__global__ void __launch_bounds__(NT, 1) __cluster_dims__(CLUSTER, 1, 1)
decoder_kernel(const float* __restrict__ z,
               const float* __restrict__ w_lh, const float* __restrict__ b_lh,
               const float* __restrict__ w_lc, const float* __restrict__ b_lc,
               const float* __restrict__ b_proj,
               float* __restrict__ out) {
    extern __shared__ __align__(16) char smem[];
    uint16_t* Ah  = (uint16_t*)smem;                 // [32][AS] bf16 hi
    uint16_t* Al  = Ah + 32 * AS;                    // [32][AS] bf16 lo
    float*    pt  = (float*)(Al + 32 * AS);          // [8][32][33] proj partials
    float*    z_s = pt + 8 * 32 * 33;                // [32][32]

    const int tid  = threadIdx.x;
    const int wid  = tid >> 5;
    const int lane = tid & 31;
    const int tig  = lane & 3;
    const int odd  = lane & 1;
    const int colw = wid >> 1;                       // 0..7 column block within CTA
    const int mt   = wid & 1;                        // m-tile (16-row half)
    uint32_t cr;
    asm("mov.u32 %0, %%cluster_ctarank;" : "=r"(cr));
    const int slot = (int)cr * 8 + colw;             // global column-owner slot
    const int r0   = (blockIdx.x / CLUSTER) * ROWS;
    const int ubase  = slot * 16 + (tig >> 1);
    const int rbaseA = (lane >> 2) + (odd ? 8 : 0);  // row within m-tile
    const int myrow  = mt * 16 + rbaseA;             // row within 32-row slab

    // ---- stage z; init x-pad cols 0..31 (col 20 = 1.0 bias column) ----
    for (int i = tid; i < ROWS * LATD; i += NT) z_s[i] = z[(size_t)r0 * LATD + i];
    for (int i = tid; i < 32 * 32; i += NT) {
        int r = i >> 5, c = i & 31;
        Ah[r * AS + c] = (c == 20) ? (uint16_t)0x3F80 : (uint16_t)0;
        Al[r * AS + c] = 0;
    }
    __syncthreads();

    // ---- c-state init in C-fragment layout (own units, own m-tile rows) ----
    float c0st[8], c1st[8];
    #pragma unroll
    for (int nt = 0; nt < 8; ++nt) {
        int u = ubase + nt * 2;
        float s0 = b_lc[u], s1 = b_lc[HID + u];
        for (int k = 0; k < LATD; ++k) {
            float wa = __ldg(w_lc + (size_t)u * LATD + k);
            float wb = __ldg(w_lc + (size_t)(HID + u) * LATD + k);
            float zv = z_s[myrow * LATD + k];
            s0 = fmaf(zv, wa, s0);  s1 = fmaf(zv, wb, s1);
        }
        c0st[nt] = s0;  c1st[nt] = s1;
    }

    // ---- h-state init into Ah/Al: each CTA fills the FULL A (redundant, init-only) ----
    {
        int u2 = tid & 255, rb = (tid >> 8) * 16;
        float h0v[16], h1v[16];
        #pragma unroll
        for (int r = 0; r < 16; ++r) { h0v[r] = b_lh[u2]; h1v[r] = b_lh[HID + u2]; }
        for (int k = 0; k < LATD; ++k) {
            float wa = __ldg(w_lh + (size_t)u2 * LATD + k);
            float wb = __ldg(w_lh + (size_t)(HID + u2) * LATD + k);
            #pragma unroll
            for (int r = 0; r < 16; ++r) {
                float zv = z_s[(rb + r) * LATD + k];
                h0v[r] = fmaf(zv, wa, h0v[r]);
                h1v[r] = fmaf(zv, wb, h1v[r]);
            }
        }
        #pragma unroll
        for (int r = 0; r < 16; ++r) {
            unsigned short hh, hl;
            split2(h0v[r], hh, hl);
            Ah[(rb + r) * AS + H0C + u2] = hh;  Al[(rb + r) * AS + H0C + u2] = hl;
            split2(h1v[r], hh, hl);
            Ah[(rb + r) * AS + H1C + u2] = hh;  Al[(rb + r) * AS + H1C + u2] = hl;
        }
    }
    __syncthreads();

    const uint32_t AhB = smem_u32(Ah);
    const uint32_t AlB = smem_u32(Al);
    const uint32_t pAh = mapa_sh(AhB, cr ^ 1u);
    const uint32_t pAl = mapa_sh(AlB, cr ^ 1u);
    const uint32_t aH = AhB + mt * MTOFF + (lane & 15) * ROWB + (lane >> 4) * 16;
    const uint32_t aL = AlB + mt * MTOFF + (lane & 15) * ROWB + (lane >> 4) * 16;
    const uint4* wf0 = g_W0 + (size_t)slot * KS0 * 256 + lane;
    const uint4* wf1 = g_W1 + (size_t)slot * KS1 * 256 + lane;
    const uint4* wfP = g_PJ + (size_t)colw * 256 + lane;
    const bool packlead = (lane & 2) == 0;           // lanes pairing via xor 2

    cluster_sync_();

    // =============================== time loop ===============================
    for (int t = 0; t < TST; ++t) {
        uint32_t hp[8];

        // ---- layer 0 : reads cols 0..287 ----
        #pragma unroll
        for (int half = 0; half < 2; ++half) {
            float acc[4][4];
            mma_tile<KS0, 256>(aH, aL, wf0 + half * 128, acc);
            lstm_epi(acc, half, odd, c0st, hp);
        }
        cluster_sync_();                              // both CTAs done reading h0_old
        #pragma unroll
        for (int nt = 0; nt < 8; ++nt) {
            uint32_t oth = __shfl_xor_sync(0xffffffffu, hp[nt], 2);
            if (packlead) {
                uint32_t hi2 = (hp[nt] & 0xffffu) | (oth << 16);
                uint32_t lo2 = (hp[nt] >> 16)     | (oth & 0xffff0000u);
                int u = ubase + nt * 2;              // even
                uint32_t off = (uint32_t)(myrow * AS + H0C + u) * 2;
                *reinterpret_cast<uint32_t*>(&Ah[myrow * AS + H0C + u]) = hi2;
                *reinterpret_cast<uint32_t*>(&Al[myrow * AS + H0C + u]) = lo2;
                st_remote_u32(pAh + off, hi2);
                st_remote_u32(pAl + off, lo2);
            }
        }
        cluster_sync_();                              // new h0 visible cluster-wide

        // ---- layer 1 : reads cols 16..543 ----
        #pragma unroll
        for (int half = 0; half < 2; ++half) {
            float acc[4][4];
            mma_tile<KS1, 256>(aH + 32, aL + 32, wf1 + half * 128, acc);
            lstm_epi(acc, half, odd, c1st, hp);
        }
        cluster_sync_();                              // both CTAs done reading h1_old
        #pragma unroll
        for (int nt = 0; nt < 8; ++nt) {
            uint32_t oth = __shfl_xor_sync(0xffffffffu, hp[nt], 2);
            if (packlead) {
                uint32_t hi2 = (hp[nt] & 0xffffu) | (oth << 16);
                uint32_t lo2 = (hp[nt] >> 16)     | (oth & 0xffff0000u);
                int u = ubase + nt * 2;
                uint32_t off = (uint32_t)(myrow * AS + H1C + u) * 2;
                *reinterpret_cast<uint32_t*>(&Ah[myrow * AS + H1C + u]) = hi2;
                *reinterpret_cast<uint32_t*>(&Al[myrow * AS + H1C + u]) = lo2;
                st_remote_u32(pAh + off, hi2);
                st_remote_u32(pAl + off, lo2);
            }
        }
        cluster_sync_();                              // new h1 visible cluster-wide

        // ---- projection MMA: 8 K-slices x 2 m-tiles across 16 warps ----
        {
            float acc[4][4];
            mma_tile<2, 128>(aH + 2 * H1C + colw * 64, aL + 2 * H1C + colw * 64, wfP, acc);
            #pragma unroll
            for (int n = 0; n < 4; ++n) {
                int rr = mt * 16 + (lane >> 2);
                float* p = pt + colw * 1056 + rr * 33 + n * 8 + tig * 2;
                p[0]          = acc[n][0];
                p[1]          = acc[n][1];
                p[8 * 33]     = acc[n][2];
                p[8 * 33 + 1] = acc[n][3];
            }
        }
        __syncthreads();

        // ---- reduce partials + bias; rank writes its half of rows to gmem; feed back x ----
        for (int o = tid; o < ROWS * DIM; o += NT) {
            int r = o / DIM, d = o - r * DIM;
            float y = __ldg(b_proj + d);
            #pragma unroll
            for (int w8 = 0; w8 < 8; ++w8) y += pt[w8 * 1056 + r * 33 + d];
            if ((uint32_t)(r >> 4) == cr)
                out[(size_t)(r0 + r) * (TST * DIM) + (size_t)t * DIM + d] = y;
            unsigned short hh, hl;
            split2(y, hh, hl);
            Ah[r * AS + d] = hh;
            Al[r * AS + d] = hl;
        }
        __syncthreads();
    }
}

extern "C" void kernel_launch(void* const* d_in, const int* in_sizes, int n_in,
                              void* d_out, int out_size) {
    const int wbase = (n_in >= 17) ? 3 : 2;

    const float* z      = (const float*)d_in[0];
    const float* w_lh   = (const float*)d_in[wbase + 0];
    const float* b_lh   = (const float*)d_in[wbase + 1];
    const float* w_lc   = (const float*)d_in[wbase + 2];
    const float* b_lc   = (const float*)d_in[wbase + 3];
    const float* w_ih0  = (const float*)d_in[wbase + 4];
    const float* w_hh0  = (const float*)d_in[wbase + 5];
    const float* b_ih0  = (const float*)d_in[wbase + 6];
    const float* b_hh0  = (const float*)d_in[wbase + 7];
    const float* w_ih1  = (const float*)d_in[wbase + 8];
    const float* w_hh1  = (const float*)d_in[wbase + 9];
    const float* b_ih1  = (const float*)d_in[wbase + 10];
    const float* b_hh1  = (const float*)d_in[wbase + 11];
    const float* w_proj = (const float*)d_in[wbase + 12];
    const float* b_proj = (const float*)d_in[wbase + 13];

    static bool attr_set = false;
    if (!attr_set) {
        cudaFuncSetAttribute(decoder_kernel,
                             cudaFuncAttributeMaxDynamicSharedMemorySize, SMEM_BYTES);
        attr_set = true;
    }

    repack_kernel<<<512, 256>>>(w_ih0, w_hh0, b_ih0, b_hh0,
                                w_ih1, w_hh1, b_ih1, b_hh1, w_proj);
    decoder_kernel<<<NCTA, NT, SMEM_BYTES>>>(z, w_lh, b_lh, w_lc, b_lc,
                                             b_proj, (float*)d_out);
}

// round 10
// speedup vs baseline: 1.0084x; 1.0084x over previous
#include <cuda_runtime.h>
#include <cuda_bf16.h>
#include <cstdint>

#define BATCH   2048
#define LATD    32
#define HID     256
#define DIM     20
#define TST     512

#define ROWS    32                 // batch rows per CLUSTER
#define CLUSTER 2
#define NCTA    ((BATCH / ROWS) * CLUSTER)   // 128
#define NT      512                // 16 warps per CTA, each owns 32 gate columns
#define NSLOT   32                 // global column-owner slots (2 CTAs x 16)

#define KS0     18                 // layer0: cols 0..287  (x|1|0|h0)
#define KS1     33                 // layer1: cols 16..543 (..|1|..|h0|h1)
#define AS      552                // u16 elements per activation row
#define ROWB    (AS * 2)           // bytes per row
#define MTOFF   (16 * ROWB)        // m-tile 1 byte offset
#define H0C     32
#define H1C     288

#define SMEM_BYTES (32*AS*2*2 + 8*32*33*4 + ROWS*LATD*4)   // 108544

// ---------------- fragment-major packed weights (repacked each launch) ----------------
// layout: [slot][ks][nt(4)][lane]
__device__ uint4 g_W0[NSLOT * KS0 * 4 * 32];
__device__ uint4 g_W1[NSLOT * KS1 * 4 * 32];
__device__ uint4 g_PJ[8 * 2 * 4 * 32];

// ---------------- helpers ----------------
__device__ __forceinline__ float sigm(float x) {
    return __fdividef(1.f, 1.f + __expf(-x));
}
__device__ __forceinline__ float tanh_(float x) {
    float e = __expf(2.f * x);
    return 1.f - __fdividef(2.f, e + 1.f);
}
__device__ __forceinline__ void split2(float x, unsigned short& hi, unsigned short& lo) {
    __nv_bfloat16 h = __float2bfloat16_rn(x);
    hi = __bfloat16_as_ushort(h);
    lo = __bfloat16_as_ushort(__float2bfloat16_rn(x - __bfloat162float(h)));
}
__device__ __forceinline__ uint32_t smem_u32(const void* p) {
    uint32_t a;
    asm("{ .reg .u64 t; cvta.to.shared.u64 t, %1; cvt.u32.u64 %0, t; }" : "=r"(a) : "l"(p));
    return a;
}
__device__ __forceinline__ uint32_t mapa_sh(uint32_t addr, uint32_t rank) {
    uint32_t r;
    asm("mapa.shared::cluster.u32 %0, %1, %2;" : "=r"(r) : "r"(addr), "r"(rank));
    return r;
}
__device__ __forceinline__ void st_remote_u32(uint32_t addr, uint32_t v) {
    asm volatile("st.shared::cluster.u32 [%0], %1;" :: "r"(addr), "r"(v) : "memory");
}
__device__ __forceinline__ void cluster_sync_() {
    asm volatile("barrier.cluster.arrive.aligned;" ::: "memory");
    asm volatile("barrier.cluster.wait.aligned;" ::: "memory");
}
__device__ __forceinline__ void ldsm4(uint32_t& r0, uint32_t& r1, uint32_t& r2, uint32_t& r3,
                                      uint32_t a) {
    asm volatile("ldmatrix.sync.aligned.m8n8.x4.shared.b16 {%0,%1,%2,%3}, [%4];"
                 : "=r"(r0), "=r"(r1), "=r"(r2), "=r"(r3) : "r"(a));
}
__device__ __forceinline__ void mma16816(float* c, uint32_t a0, uint32_t a1, uint32_t a2,
                                         uint32_t a3, uint32_t b0, uint32_t b1) {
    asm volatile(
        "mma.sync.aligned.m16n8k16.row.col.f32.bf16.bf16.f32 "
        "{%0,%1,%2,%3}, {%4,%5,%6,%7}, {%8,%9}, {%0,%1,%2,%3};"
        : "+f"(c[0]), "+f"(c[1]), "+f"(c[2]), "+f"(c[3])
        : "r"(a0), "r"(a1), "r"(a2), "r"(a3), "r"(b0), "r"(b1));
}

// ---------------- repack: weight element accessors (kc = activation column) ----------------
__device__ __forceinline__ float W0val(int kc, int n,
                                       const float* w_ih0, const float* w_hh0,
                                       const float* b_ih0, const float* b_hh0) {
    int u = n >> 2, g = n & 3, row = g * HID + u;
    if (kc < DIM)  return w_ih0[row * DIM + kc];
    if (kc == 20)  return b_ih0[row] + b_hh0[row];
    if (kc < 32)   return 0.f;
    return w_hh0[row * HID + (kc - 32)];
}
__device__ __forceinline__ float W1val(int kc, int n,
                                       const float* w_ih1, const float* w_hh1,
                                       const float* b_ih1, const float* b_hh1) {
    int u = n >> 2, g = n & 3, row = g * HID + u;
    if (kc == 20)  return b_ih1[row] + b_hh1[row];
    if (kc >= 288) return w_hh1[row * HID + (kc - 288)];
    if (kc >= 32)  return w_ih1[row * HID + (kc - 32)];
    return 0.f;
}
__device__ __forceinline__ uint4 pack_frag(float e00, float e01, float e10, float e11) {
    unsigned short h00, l00, h01, l01, h10, l10, h11, l11;
    split2(e00, h00, l00); split2(e01, h01, l01);
    split2(e10, h10, l10); split2(e11, h11, l11);
    uint4 v;
    v.x = (uint32_t)h00 | ((uint32_t)h01 << 16);
    v.y = (uint32_t)h10 | ((uint32_t)h11 << 16);
    v.z = (uint32_t)l00 | ((uint32_t)l01 << 16);
    v.w = (uint32_t)l10 | ((uint32_t)l11 << 16);
    return v;
}

__global__ void repack_kernel(const float* __restrict__ w_ih0, const float* __restrict__ w_hh0,
                              const float* __restrict__ b_ih0, const float* __restrict__ b_hh0,
                              const float* __restrict__ w_ih1, const float* __restrict__ w_hh1,
                              const float* __restrict__ b_ih1, const float* __restrict__ b_hh1,
                              const float* __restrict__ w_proj) {
    const int stride = gridDim.x * blockDim.x;
    const int base   = blockIdx.x * blockDim.x + threadIdx.x;

    const int N0 = NSLOT * KS0 * 4 * 32;
    for (int idx = base; idx < N0; idx += stride) {
        int lane = idx & 31, t = idx >> 5;
        int nt = t & 3; t >>= 2;
        int ks = t % KS0, s = t / KS0;
        int n  = s * 32 + nt * 8 + (lane >> 2);
        int kc = ks * 16 + (lane & 3) * 2;
        g_W0[idx] = pack_frag(W0val(kc,     n, w_ih0, w_hh0, b_ih0, b_hh0),
                              W0val(kc + 1, n, w_ih0, w_hh0, b_ih0, b_hh0),
                              W0val(kc + 8, n, w_ih0, w_hh0, b_ih0, b_hh0),
                              W0val(kc + 9, n, w_ih0, w_hh0, b_ih0, b_hh0));
    }
    const int N1 = NSLOT * KS1 * 4 * 32;
    for (int idx = base; idx < N1; idx += stride) {
        int lane = idx & 31, t = idx >> 5;
        int nt = t & 3; t >>= 2;
        int ks = t % KS1, s = t / KS1;
        int n  = s * 32 + nt * 8 + (lane >> 2);
        int kc = 16 + ks * 16 + (lane & 3) * 2;
        g_W1[idx] = pack_frag(W1val(kc,     n, w_ih1, w_hh1, b_ih1, b_hh1),
                              W1val(kc + 1, n, w_ih1, w_hh1, b_ih1, b_hh1),
                              W1val(kc + 8, n, w_ih1, w_hh1, b_ih1, b_hh1),
                              W1val(kc + 9, n, w_ih1, w_hh1, b_ih1, b_hh1));
    }
    const int NP = 8 * 2 * 4 * 32;
    for (int idx = base; idx < NP; idx += stride) {
        int lane = idx & 31, t = idx >> 5;
        int nt = t & 3; t >>= 2;
        int ks = t & 1, w = t >> 1;
        int n  = nt * 8 + (lane >> 2);
        int kc = w * 32 + ks * 16 + (lane & 3) * 2;
        float e00 = (n < DIM) ? w_proj[n * HID + kc]     : 0.f;
        float e01 = (n < DIM) ? w_proj[n * HID + kc + 1] : 0.f;
        float e10 = (n < DIM) ? w_proj[n * HID + kc + 8] : 0.f;
        float e11 = (n < DIM) ? w_proj[n * HID + kc + 9] : 0.f;
        g_PJ[idx] = pack_frag(e00, e01, e10, e11);
    }
}

// ---------------- gates MMA: 4 n-tiles x 2 m-tiles, 3-pass bf16-split ----------------
template <int KSTEPS>
__device__ __forceinline__ void mma_gates(uint32_t aHi, uint32_t aLo,
                                          const uint4* __restrict__ wf,
                                          float (&acc)[2][4][4]) {
    #pragma unroll
    for (int mt = 0; mt < 2; ++mt)
        #pragma unroll
        for (int n = 0; n < 4; ++n)
            #pragma unroll
            for (int i = 0; i < 4; ++i) acc[mt][n][i] = 0.f;

    #pragma unroll 2
    for (int ks = 0; ks < KSTEPS; ++ks) {
        uint32_t h0, h1, h2, h3, h4, h5, h6, h7;
        uint32_t l0, l1, l2, l3, l4, l5, l6, l7;
        ldsm4(h0, h1, h2, h3, aHi + ks * 32);
        ldsm4(h4, h5, h6, h7, aHi + MTOFF + ks * 32);
        ldsm4(l0, l1, l2, l3, aLo + ks * 32);
        ldsm4(l4, l5, l6, l7, aLo + MTOFF + ks * 32);
        #pragma unroll
        for (int n = 0; n < 4; ++n) {
            uint4 B = __ldg(wf + (size_t)ks * 128 + n * 32);
            mma16816(acc[0][n], h0, h1, h2, h3, B.x, B.y);   // hiA*hiB
            mma16816(acc[0][n], l0, l1, l2, l3, B.x, B.y);   // loA*hiB
            mma16816(acc[0][n], h0, h1, h2, h3, B.z, B.w);   // hiA*loB
            mma16816(acc[1][n], h4, h5, h6, h7, B.x, B.y);
            mma16816(acc[1][n], l4, l5, l6, l7, B.x, B.y);
            mma16816(acc[1][n], h4, h5, h6, h7, B.z, B.w);
        }
    }
}

// ---------------- projection MMA: single m-tile, 4 n-tiles ----------------
__device__ __forceinline__ void mma_proj(uint32_t aHi, uint32_t aLo,
                                         const uint4* __restrict__ wf,
                                         float (&acc)[4][4]) {
    #pragma unroll
    for (int n = 0; n < 4; ++n)
        #pragma unroll
        for (int i = 0; i < 4; ++i) acc[n][i] = 0.f;
    #pragma unroll
    for (int ks = 0; ks < 2; ++ks) {
        uint32_t h0, h1, h2, h3, l0, l1, l2, l3;
        ldsm4(h0, h1, h2, h3, aHi + ks * 32);
        ldsm4(l0, l1, l2, l3, aLo + ks * 32);
        #pragma unroll
        for (int n = 0; n < 4; ++n) {
            uint4 B = __ldg(wf + (size_t)ks * 128 + n * 32);
            mma16816(acc[n], h0, h1, h2, h3, B.x, B.y);
            mma16816(acc[n], l0, l1, l2, l3, B.x, B.y);
            mma16816(acc[n], h0, h1, h2, h3, B.z, B.w);
        }
    }
}

// ---------------- LSTM epilogue for 4 n-tiles of one m-tile ----------------
__device__ __forceinline__ void lstm_epi(float (&acc)[4][4], int odd,
                                         float (&cs)[4], uint32_t (&hp)[4]) {
    #pragma unroll
    for (int n = 0; n < 4; ++n) {
        float a0 = acc[n][0], a1 = acc[n][1];
        float a2 = acc[n][2], a3 = acc[n][3];
        float t0 = __shfl_xor_sync(0xffffffffu, a0, 1);
        float t1 = __shfl_xor_sync(0xffffffffu, a1, 1);
        float t2 = __shfl_xor_sync(0xffffffffu, a2, 1);
        float t3 = __shfl_xor_sync(0xffffffffu, a3, 1);
        float gi = odd ? t2 : a0;
        float gf = odd ? t3 : a1;
        float gg = odd ? a2 : t0;
        float go = odd ? a3 : t1;
        float c = sigm(gf) * cs[n] + sigm(gi) * tanh_(gg);
        cs[n] = c;
        float h = sigm(go) * tanh_(c);
        unsigned short hh, hl;
        split2(h, hh, hl);
        hp[n] = (uint32_t)hh | ((uint32_t)hl << 16);
    }
}

// ---------------- packed h write-back (local + remote) ----------------
__device__ __forceinline__ void store_h(uint32_t (&hp)[2][4], int ubase,
                                        const int* myrow, int colbase,
                                        uint16_t* Ah, uint16_t* Al,
                                        uint32_t pAh, uint32_t pAl, bool packlead) {
    #pragma unroll
    for (int mt = 0; mt < 2; ++mt)
        #pragma unroll
        for (int nt = 0; nt < 4; ++nt) {
            uint32_t oth = __shfl_xor_sync(0xffffffffu, hp[mt][nt], 2);
            if (packlead) {
                uint32_t hi2 = (hp[mt][nt] & 0xffffu) | (oth << 16);
                uint32_t lo2 = (hp[mt][nt] >> 16)     | (oth & 0xffff0000u);
                int u = ubase + nt * 2;              // even unit
                int r = myrow[mt];
                uint32_t off = (uint32_t)(r * AS + colbase + u) * 2;
                *reinterpret_cast<uint32_t*>(&Ah[r * AS + colbase + u]) = hi2;
                *reinterpret_cast<uint32_t*>(&Al[r * AS + colbase + u]) = lo2;
                st_remote_u32(pAh + off, hi2);
                st_remote_u32(pAl + off, lo2);
            }
        }
}

// ---------------- main persistent clustered kernel ----------------
__global__ void __launch_bounds__(NT, 1) __cluster_dims__(CLUSTER, 1, 1)
decoder_kernel(const float* __restrict__ z,
               const float* __restrict__ w_lh, const float* __restrict__ b_lh,
               const float* __restrict__ w_lc, const float* __restrict__ b_lc,
               const float* __restrict__ b_proj,
               float* __restrict__ out) {
    extern __shared__ __align__(16) char smem[];
    uint16_t* Ah  = (uint16_t*)smem;                 // [32][AS] bf16 hi
    uint16_t* Al  = Ah + 32 * AS;                    // [32][AS] bf16 lo
    float*    pt  = (float*)(Al + 32 * AS);          // [8][32][33] proj partials
    float*    z_s = pt + 8 * 32 * 33;                // [32][32]

    const int tid  = threadIdx.x;
    const int wid  = tid >> 5;
    const int lane = tid & 31;
    const int tig  = lane & 3;
    const int odd  = lane & 1;
    uint32_t cr;
    asm("mov.u32 %0, %%cluster_ctarank;" : "=r"(cr));
    const int slot = (int)cr * 16 + wid;             // 0..31 column-owner slot
    const int r0   = (blockIdx.x / CLUSTER) * ROWS;
    const int ubase  = slot * 8 + (tig >> 1);
    const int rbaseA = (lane >> 2) + (odd ? 8 : 0);  // row within m-tile
    const int myrow[2] = { rbaseA, 16 + rbaseA };
    const bool packlead = (lane & 2) == 0;

    // ---- stage z; init x-pad cols 0..31 (col 20 = 1.0 bias column) ----
    for (int i = tid; i < ROWS * LATD; i += NT) z_s[i] = z[(size_t)r0 * LATD + i];
    for (int i = tid; i < 32 * 32; i += NT) {
        int r = i >> 5, c = i & 31;
        Ah[r * AS + c] = (c == 20) ? (uint16_t)0x3F80 : (uint16_t)0;
        Al[r * AS + c] = 0;
    }
    __syncthreads();

    // ---- c-state init in C-fragment layout (own units, both m-tiles) ----
    float c0st[2][4], c1st[2][4];
    #pragma unroll
    for (int mt = 0; mt < 2; ++mt)
        #pragma unroll
        for (int nt = 0; nt < 4; ++nt) {
            int u = ubase + nt * 2;
            float s0 = b_lc[u], s1 = b_lc[HID + u];
            for (int k = 0; k < LATD; ++k) {
                float wa = __ldg(w_lc + (size_t)u * LATD + k);
                float wb = __ldg(w_lc + (size_t)(HID + u) * LATD + k);
                float zv = z_s[myrow[mt] * LATD + k];
                s0 = fmaf(zv, wa, s0);  s1 = fmaf(zv, wb, s1);
            }
            c0st[mt][nt] = s0;  c1st[mt][nt] = s1;
        }

    // ---- h-state init into Ah/Al: each CTA fills the FULL A (redundant, init-only) ----
    {
        int u2 = tid & 255, rb = (tid >> 8) * 16;
        float h0v[16], h1v[16];
        #pragma unroll
        for (int r = 0; r < 16; ++r) { h0v[r] = b_lh[u2]; h1v[r] = b_lh[HID + u2]; }
        for (int k = 0; k < LATD; ++k) {
            float wa = __ldg(w_lh + (size_t)u2 * LATD + k);
            float wb = __ldg(w_lh + (size_t)(HID + u2) * LATD + k);
            #pragma unroll
            for (int r = 0; r < 16; ++r) {
                float zv = z_s[(rb + r) * LATD + k];
                h0v[r] = fmaf(zv, wa, h0v[r]);
                h1v[r] = fmaf(zv, wb, h1v[r]);
            }
        }
        #pragma unroll
        for (int r = 0; r < 16; ++r) {
            unsigned short hh, hl;
            split2(h0v[r], hh, hl);
            Ah[(rb + r) * AS + H0C + u2] = hh;  Al[(rb + r) * AS + H0C + u2] = hl;
            split2(h1v[r], hh, hl);
            Ah[(rb + r) * AS + H1C + u2] = hh;  Al[(rb + r) * AS + H1C + u2] = hl;
        }
    }
    __syncthreads();

    const uint32_t AhB = smem_u32(Ah);
    const uint32_t AlB = smem_u32(Al);
    const uint32_t pAh = mapa_sh(AhB, cr ^ 1u);
    const uint32_t pAl = mapa_sh(AlB, cr ^ 1u);
    const uint32_t aH = AhB + (lane & 15) * ROWB + (lane >> 4) * 16;
    const uint32_t aL = AlB + (lane & 15) * ROWB + (lane >> 4) * 16;
    const uint4* wf0 = g_W0 + (size_t)slot * KS0 * 128 + lane;
    const uint4* wf1 = g_W1 + (size_t)slot * KS1 * 128 + lane;
    const int pk = wid >> 1;                        // proj K-slice 0..7
    const int pm = wid & 1;                         // proj m-tile
    const uint4* wfP = g_PJ + (size_t)pk * 256 + lane;

    cluster_sync_();

    // =============================== time loop ===============================
    for (int t = 0; t < TST; ++t) {
        uint32_t hp[2][4];
        float acc[2][4][4];

        // ---- layer 0 : reads cols 0..287 ----
        mma_gates<KS0>(aH, aL, wf0, acc);
        lstm_epi(acc[0], odd, c0st[0], hp[0]);
        lstm_epi(acc[1], odd, c0st[1], hp[1]);
        cluster_sync_();                              // both CTAs done reading h0_old
        store_h(hp, ubase, myrow, H0C, Ah, Al, pAh, pAl, packlead);
        cluster_sync_();                              // new h0 visible cluster-wide

        // ---- layer 1 : reads cols 16..543 ----
        mma_gates<KS1>(aH + 32, aL + 32, wf1, acc);
        lstm_epi(acc[0], odd, c1st[0], hp[0]);
        lstm_epi(acc[1], odd, c1st[1], hp[1]);
        cluster_sync_();                              // both CTAs done reading h1_old
        store_h(hp, ubase, myrow, H1C, Ah, Al, pAh, pAl, packlead);
        cluster_sync_();                              // new h1 visible cluster-wide

        // ---- projection MMA: 8 K-slices x 2 m-tiles across 16 warps ----
        {
            float pac[4][4];
            mma_proj(aH + pm * MTOFF + 2 * H1C + pk * 64,
                     aL + pm * MTOFF + 2 * H1C + pk * 64, wfP, pac);
            #pragma unroll
            for (int n = 0; n < 4; ++n) {
                int rr = pm * 16 + (lane >> 2);
                float* p = pt + pk * 1056 + rr * 33 + n * 8 + tig * 2;
                p[0]          = pac[n][0];
                p[1]          = pac[n][1];
                p[8 * 33]     = pac[n][2];
                p[8 * 33 + 1] = pac[n][3];
            }
        }
        __syncthreads();

        // ---- reduce partials + bias; rank writes its half of rows to gmem; feed back x ----
        for (int o = tid; o < ROWS * DIM; o += NT) {
            int r = o / DIM, d = o - r * DIM;
            float y = __ldg(b_proj + d);
            #pragma unroll
            for (int w8 = 0; w8 < 8; ++w8) y += pt[w8 * 1056 + r * 33 + d];
            if ((uint32_t)(r >> 4) == cr)
                out[(size_t)(r0 + r) * (TST * DIM) + (size_t)t * DIM + d] = y;
            unsigned short hh, hl;
            split2(y, hh, hl);
            Ah[r * AS + d] = hh;
            Al[r * AS + d] = hl;
        }
        __syncthreads();
    }
}

extern "C" void kernel_launch(void* const* d_in, const int* in_sizes, int n_in,
                              void* d_out, int out_size) {
    const int wbase = (n_in >= 17) ? 3 : 2;

    const float* z      = (const float*)d_in[0];
    const float* w_lh   = (const float*)d_in[wbase + 0];
    const float* b_lh   = (const float*)d_in[wbase + 1];
    const float* w_lc   = (const float*)d_in[wbase + 2];
    const float* b_lc   = (const float*)d_in[wbase + 3];
    const float* w_ih0  = (const float*)d_in[wbase + 4];
    const float* w_hh0  = (const float*)d_in[wbase + 5];
    const float* b_ih0  = (const float*)d_in[wbase + 6];
    const float* b_hh0  = (const float*)d_in[wbase + 7];
    const float* w_ih1  = (const float*)d_in[wbase + 8];
    const float* w_hh1  = (const float*)d_in[wbase + 9];
    const float* b_ih1  = (const float*)d_in[wbase + 10];
    const float* b_hh1  = (const float*)d_in[wbase + 11];
    const float* w_proj = (const float*)d_in[wbase + 12];
    const float* b_proj = (const float*)d_in[wbase + 13];

    static bool attr_set = false;
    if (!attr_set) {
        cudaFuncSetAttribute(decoder_kernel,
                             cudaFuncAttributeMaxDynamicSharedMemorySize, SMEM_BYTES);
        attr_set = true;
    }

    repack_kernel<<<512, 256>>>(w_ih0, w_hh0, b_ih0, b_hh0,
                                w_ih1, w_hh1, b_ih1, b_hh1, w_proj);
    decoder_kernel<<<NCTA, NT, SMEM_BYTES>>>(z, w_lh, b_lh, w_lc, b_lc,
                                             b_proj, (float*)d_out);
}

// round 11
// speedup vs baseline: 1.3213x; 1.3103x over previous
#include <cuda_runtime.h>
#include <cuda_fp16.h>
#include <cstdint>

#define BATCH   2048
#define LATD    32
#define HID     256
#define DIM     20
#define TST     512

#define ROWS    32                 // batch rows per CLUSTER
#define CLUSTER 2
#define NCTA    ((BATCH / ROWS) * CLUSTER)   // 128
#define NT      256                // 8 warps per CTA (R8 config)
#define NWCTA   8
#define NSLOT   16                 // global column-owner slots (2 CTAs x 8)

#define KS0     18                 // layer0: cols 0..287  (x|1|0|h0)
#define KS1     33                 // layer1: cols 16..543 (..|1|..|h0|h1)
#define AS      552                // u16 elements per activation row
#define ROWB    (AS * 2)           // bytes per row
#define MTOFF   (16 * ROWB)        // m-tile 1 byte offset
#define H0C     32
#define H1C     288

#define SMEM_BYTES (32*AS*2*2 + 8*32*33*4 + ROWS*LATD*4)   // 108544

// ---------------- fragment-major packed fp16 weights (repacked each launch) ----------------
// gates layout: [slot][ks][half(2)][pp(2)][lane]  (uint4 = 2 n-tiles x {b0,b1})
__device__ uint4 g_W0[NSLOT * KS0 * 4 * 32];
__device__ uint4 g_W1[NSLOT * KS1 * 4 * 32];
__device__ uint4 g_PJ[8 * 2 * 2 * 32];      // [pk][ks][pp][lane]

// ---------------- helpers ----------------
__device__ __forceinline__ float sigm(float x) {
    return __fdividef(1.f, 1.f + __expf(-x));
}
__device__ __forceinline__ float tanh_(float x) {
    float e = __expf(2.f * x);
    return 1.f - __fdividef(2.f, e + 1.f);
}
// fp16 hi/lo split: x = hi + lo with |err| ~ 2^-22 * |x|
__device__ __forceinline__ void split2h(float x, unsigned short& hi, unsigned short& lo) {
    __half h = __float2half_rn(x);
    hi = __half_as_ushort(h);
    lo = __half_as_ushort(__float2half_rn(x - __half2float(h)));
}
__device__ __forceinline__ uint32_t f16x2(float a, float b) {
    unsigned short ha = __half_as_ushort(__float2half_rn(a));
    unsigned short hb = __half_as_ushort(__float2half_rn(b));
    return (uint32_t)ha | ((uint32_t)hb << 16);
}
__device__ __forceinline__ uint32_t smem_u32(const void* p) {
    uint32_t a;
    asm("{ .reg .u64 t; cvta.to.shared.u64 t, %1; cvt.u32.u64 %0, t; }" : "=r"(a) : "l"(p));
    return a;
}
__device__ __forceinline__ uint32_t mapa_sh(uint32_t addr, uint32_t rank) {
    uint32_t r;
    asm("mapa.shared::cluster.u32 %0, %1, %2;" : "=r"(r) : "r"(addr), "r"(rank));
    return r;
}
__device__ __forceinline__ void st_remote_u16(uint32_t addr, unsigned short v) {
    asm volatile("st.shared::cluster.u16 [%0], %1;" :: "r"(addr), "h"(v) : "memory");
}
__device__ __forceinline__ void cluster_sync_() {
    asm volatile("barrier.cluster.arrive.aligned;" ::: "memory");
    asm volatile("barrier.cluster.wait.aligned;" ::: "memory");
}
__device__ __forceinline__ void ldsm4(uint32_t& r0, uint32_t& r1, uint32_t& r2, uint32_t& r3,
                                      uint32_t a) {
    asm volatile("ldmatrix.sync.aligned.m8n8.x4.shared.b16 {%0,%1,%2,%3}, [%4];"
                 : "=r"(r0), "=r"(r1), "=r"(r2), "=r"(r3) : "r"(a));
}
__device__ __forceinline__ void mma16816(float* c, uint32_t a0, uint32_t a1, uint32_t a2,
                                         uint32_t a3, uint32_t b0, uint32_t b1) {
    asm volatile(
        "mma.sync.aligned.m16n8k16.row.col.f32.f16.f16.f32 "
        "{%0,%1,%2,%3}, {%4,%5,%6,%7}, {%8,%9}, {%0,%1,%2,%3};"
        : "+f"(c[0]), "+f"(c[1]), "+f"(c[2]), "+f"(c[3])
        : "r"(a0), "r"(a1), "r"(a2), "r"(a3), "r"(b0), "r"(b1));
}

// ---------------- repack: weight element accessors (kc = activation column) ----------------
__device__ __forceinline__ float W0val(int kc, int n,
                                       const float* w_ih0, const float* w_hh0,
                                       const float* b_ih0, const float* b_hh0) {
    int u = n >> 2, g = n & 3, row = g * HID + u;
    if (kc < DIM)  return w_ih0[row * DIM + kc];
    if (kc == 20)  return b_ih0[row] + b_hh0[row];
    if (kc < 32)   return 0.f;
    return w_hh0[row * HID + (kc - 32)];
}
__device__ __forceinline__ float W1val(int kc, int n,
                                       const float* w_ih1, const float* w_hh1,
                                       const float* b_ih1, const float* b_hh1) {
    int u = n >> 2, g = n & 3, row = g * HID + u;
    if (kc == 20)  return b_ih1[row] + b_hh1[row];
    if (kc >= 288) return w_hh1[row * HID + (kc - 288)];
    if (kc >= 32)  return w_ih1[row * HID + (kc - 32)];
    return 0.f;
}

__global__ void repack_kernel(const float* __restrict__ w_ih0, const float* __restrict__ w_hh0,
                              const float* __restrict__ b_ih0, const float* __restrict__ b_hh0,
                              const float* __restrict__ w_ih1, const float* __restrict__ w_hh1,
                              const float* __restrict__ b_ih1, const float* __restrict__ b_hh1,
                              const float* __restrict__ w_proj) {
    const int stride = gridDim.x * blockDim.x;
    const int base   = blockIdx.x * blockDim.x + threadIdx.x;

    const int N0 = NSLOT * KS0 * 4 * 32;
    for (int idx = base; idx < N0; idx += stride) {
        int lane = idx & 31, t = idx >> 5;
        int pp = t & 1; t >>= 1;
        int hf = t & 1; t >>= 1;
        int ks = t % KS0, s = t / KS0;
        int na = s * 64 + hf * 32 + pp * 16 + (lane >> 2);
        int nb = na + 8;
        int kc = ks * 16 + (lane & 3) * 2;
        uint4 v;
        v.x = f16x2(W0val(kc,     na, w_ih0, w_hh0, b_ih0, b_hh0),
                    W0val(kc + 1, na, w_ih0, w_hh0, b_ih0, b_hh0));
        v.y = f16x2(W0val(kc + 8, na, w_ih0, w_hh0, b_ih0, b_hh0),
                    W0val(kc + 9, na, w_ih0, w_hh0, b_ih0, b_hh0));
        v.z = f16x2(W0val(kc,     nb, w_ih0, w_hh0, b_ih0, b_hh0),
                    W0val(kc + 1, nb, w_ih0, w_hh0, b_ih0, b_hh0));
        v.w = f16x2(W0val(kc + 8, nb, w_ih0, w_hh0, b_ih0, b_hh0),
                    W0val(kc + 9, nb, w_ih0, w_hh0, b_ih0, b_hh0));
        g_W0[idx] = v;
    }
    const int N1 = NSLOT * KS1 * 4 * 32;
    for (int idx = base; idx < N1; idx += stride) {
        int lane = idx & 31, t = idx >> 5;
        int pp = t & 1; t >>= 1;
        int hf = t & 1; t >>= 1;
        int ks = t % KS1, s = t / KS1;
        int na = s * 64 + hf * 32 + pp * 16 + (lane >> 2);
        int nb = na + 8;
        int kc = 16 + ks * 16 + (lane & 3) * 2;
        uint4 v;
        v.x = f16x2(W1val(kc,     na, w_ih1, w_hh1, b_ih1, b_hh1),
                    W1val(kc + 1, na, w_ih1, w_hh1, b_ih1, b_hh1));
        v.y = f16x2(W1val(kc + 8, na, w_ih1, w_hh1, b_ih1, b_hh1),
                    W1val(kc + 9, na, w_ih1, w_hh1, b_ih1, b_hh1));
        v.z = f16x2(W1val(kc,     nb, w_ih1, w_hh1, b_ih1, b_hh1),
                    W1val(kc + 1, nb, w_ih1, w_hh1, b_ih1, b_hh1));
        v.w = f16x2(W1val(kc + 8, nb, w_ih1, w_hh1, b_ih1, b_hh1),
                    W1val(kc + 9, nb, w_ih1, w_hh1, b_ih1, b_hh1));
        g_W1[idx] = v;
    }
    const int NP = 8 * 2 * 2 * 32;
    for (int idx = base; idx < NP; idx += stride) {
        int lane = idx & 31, t = idx >> 5;
        int pp = t & 1; t >>= 1;
        int ks = t & 1; t >>= 1;
        int w  = t;                                   // 0..7
        int na = pp * 16 + (lane >> 2);
        int nb = na + 8;
        int kc = w * 32 + ks * 16 + (lane & 3) * 2;
        auto PV = [&](int n, int k) -> float {
            return (n < DIM) ? w_proj[n * HID + k] : 0.f;
        };
        uint4 v;
        v.x = f16x2(PV(na, kc),     PV(na, kc + 1));
        v.y = f16x2(PV(na, kc + 8), PV(na, kc + 9));
        v.z = f16x2(PV(nb, kc),     PV(nb, kc + 1));
        v.w = f16x2(PV(nb, kc + 8), PV(nb, kc + 9));
        g_PJ[idx] = v;
    }
}

// ---------------- 2-pass fp16-split MMA over one half (4 n-tiles, 2 m-tiles) ----------------
template <int KSTEPS, int KSTRIDE>
__device__ __forceinline__ void mma_half(uint32_t aHi, uint32_t aLo,
                                         const uint4* __restrict__ wf,
                                         float (&acc)[2][4][4]) {
    #pragma unroll
    for (int mt = 0; mt < 2; ++mt)
        #pragma unroll
        for (int n = 0; n < 4; ++n)
            #pragma unroll
            for (int i = 0; i < 4; ++i) acc[mt][n][i] = 0.f;

    uint4 B0 = __ldg(wf), B1 = __ldg(wf + 32);

    #pragma unroll 2
    for (int ks = 0; ks < KSTEPS; ++ks) {
        uint4 B0n, B1n;
        if (ks + 1 < KSTEPS) {
            B0n = __ldg(wf + (size_t)(ks + 1) * KSTRIDE);
            B1n = __ldg(wf + (size_t)(ks + 1) * KSTRIDE + 32);
        }
        uint32_t h0, h1, h2, h3, h4, h5, h6, h7;
        uint32_t l0, l1, l2, l3, l4, l5, l6, l7;
        ldsm4(h0, h1, h2, h3, aHi + ks * 32);
        ldsm4(h4, h5, h6, h7, aHi + MTOFF + ks * 32);
        ldsm4(l0, l1, l2, l3, aLo + ks * 32);
        ldsm4(l4, l5, l6, l7, aLo + MTOFF + ks * 32);
        // nt0 : (B0.x, B0.y)
        mma16816(acc[0][0], h0, h1, h2, h3, B0.x, B0.y);
        mma16816(acc[0][0], l0, l1, l2, l3, B0.x, B0.y);
        mma16816(acc[1][0], h4, h5, h6, h7, B0.x, B0.y);
        mma16816(acc[1][0], l4, l5, l6, l7, B0.x, B0.y);
        // nt1 : (B0.z, B0.w)
        mma16816(acc[0][1], h0, h1, h2, h3, B0.z, B0.w);
        mma16816(acc[0][1], l0, l1, l2, l3, B0.z, B0.w);
        mma16816(acc[1][1], h4, h5, h6, h7, B0.z, B0.w);
        mma16816(acc[1][1], l4, l5, l6, l7, B0.z, B0.w);
        // nt2 : (B1.x, B1.y)
        mma16816(acc[0][2], h0, h1, h2, h3, B1.x, B1.y);
        mma16816(acc[0][2], l0, l1, l2, l3, B1.x, B1.y);
        mma16816(acc[1][2], h4, h5, h6, h7, B1.x, B1.y);
        mma16816(acc[1][2], l4, l5, l6, l7, B1.x, B1.y);
        // nt3 : (B1.z, B1.w)
        mma16816(acc[0][3], h0, h1, h2, h3, B1.z, B1.w);
        mma16816(acc[0][3], l0, l1, l2, l3, B1.z, B1.w);
        mma16816(acc[1][3], h4, h5, h6, h7, B1.z, B1.w);
        mma16816(acc[1][3], l4, l5, l6, l7, B1.z, B1.w);
        B0 = B0n;  B1 = B1n;
    }
}

// ---------------- LSTM epilogue: gate regroup via lane-pair shuffle ----------------
__device__ __forceinline__ void lstm_epi(float (&acc)[2][4][4], int half, int odd,
                                         float (&cs)[2][8], uint32_t (&hp)[2][8]) {
    #pragma unroll
    for (int mt = 0; mt < 2; ++mt) {
        #pragma unroll
        for (int n = 0; n < 4; ++n) {
            float a0 = acc[mt][n][0], a1 = acc[mt][n][1];
            float a2 = acc[mt][n][2], a3 = acc[mt][n][3];
            float t0 = __shfl_xor_sync(0xffffffffu, a0, 1);
            float t1 = __shfl_xor_sync(0xffffffffu, a1, 1);
            float t2 = __shfl_xor_sync(0xffffffffu, a2, 1);
            float t3 = __shfl_xor_sync(0xffffffffu, a3, 1);
            float gi = odd ? t2 : a0;
            float gf = odd ? t3 : a1;
            float gg = odd ? a2 : t0;
            float go = odd ? a3 : t1;
            int idx = half * 4 + n;
            float c = sigm(gf) * cs[mt][idx] + sigm(gi) * tanh_(gg);
            cs[mt][idx] = c;
            float h = sigm(go) * tanh_(c);
            unsigned short hh, hl;
            split2h(h, hh, hl);
            hp[mt][idx] = (uint32_t)hh | ((uint32_t)hl << 16);
        }
    }
}

// ---------------- main persistent clustered kernel ----------------
__global__ void __launch_bounds__(NT, 1) __cluster_dims__(CLUSTER, 1, 1)
decoder_kernel(const float* __restrict__ z,
               const float* __restrict__ w_lh, const float* __restrict__ b_lh,
               const float* __restrict__ w_lc, const float* __restrict__ b_lc,
               const float* __restrict__ b_proj,
               float* __restrict__ out) {
    extern __shared__ __align__(16) char smem[];
    uint16_t* Ah  = (uint16_t*)smem;                 // [32][AS] fp16 hi
    uint16_t* Al  = Ah + 32 * AS;                    // [32][AS] fp16 lo
    float*    pt  = (float*)(Al + 32 * AS);          // [8][32][33] proj partials
    float*    z_s = pt + 8 * 32 * 33;                // [32][32]

    const int tid  = threadIdx.x;
    const int wid  = tid >> 5;
    const int lane = tid & 31;
    const int tig  = lane & 3;
    const int odd  = lane & 1;
    uint32_t cr;
    asm("mov.u32 %0, %%cluster_ctarank;" : "=r"(cr));
    const int slot = (int)cr * NWCTA + wid;          // global column-owner slot
    const int r0   = (blockIdx.x / CLUSTER) * ROWS;
    const int ubase  = slot * 16 + (tig >> 1);
    const int rbaseA = (lane >> 2) + (odd ? 8 : 0);

    // ---- stage z; init x-pad cols 0..31 (col 20 = fp16 1.0 bias column) ----
    for (int i = tid; i < ROWS * LATD; i += NT) z_s[i] = z[(size_t)r0 * LATD + i];
    for (int i = tid; i < 32 * 32; i += NT) {
        int r = i >> 5, c = i & 31;
        Ah[r * AS + c] = (c == 20) ? (uint16_t)0x3C00 : (uint16_t)0;
        Al[r * AS + c] = 0;
    }
    __syncthreads();

    // ---- c-state init in C-fragment layout (own units, both m-tiles) ----
    float c0st[2][8], c1st[2][8];
    #pragma unroll
    for (int nt = 0; nt < 8; ++nt) {
        int u = ubase + nt * 2;
        float s00 = b_lc[u], s01 = b_lc[HID + u];
        float s10 = s00,     s11 = s01;
        for (int k = 0; k < LATD; ++k) {
            float wa = __ldg(w_lc + (size_t)u * LATD + k);
            float wb = __ldg(w_lc + (size_t)(HID + u) * LATD + k);
            float z0 = z_s[rbaseA * LATD + k];
            float z1 = z_s[(16 + rbaseA) * LATD + k];
            s00 = fmaf(z0, wa, s00);  s01 = fmaf(z0, wb, s01);
            s10 = fmaf(z1, wa, s10);  s11 = fmaf(z1, wb, s11);
        }
        c0st[0][nt] = s00;  c1st[0][nt] = s01;
        c0st[1][nt] = s10;  c1st[1][nt] = s11;
    }

    // ---- h-state init into Ah/Al: each CTA fills the FULL A (redundant, init-only) ----
    {
        int u2 = tid;                                // 0..255
        for (int rb = 0; rb < 32; rb += 16) {
            float h0v[16], h1v[16];
            #pragma unroll
            for (int r = 0; r < 16; ++r) { h0v[r] = b_lh[u2]; h1v[r] = b_lh[HID + u2]; }
            for (int k = 0; k < LATD; ++k) {
                float wa = __ldg(w_lh + (size_t)u2 * LATD + k);
                float wb = __ldg(w_lh + (size_t)(HID + u2) * LATD + k);
                #pragma unroll
                for (int r = 0; r < 16; ++r) {
                    float zv = z_s[(rb + r) * LATD + k];
                    h0v[r] = fmaf(zv, wa, h0v[r]);
                    h1v[r] = fmaf(zv, wb, h1v[r]);
                }
            }
            #pragma unroll
            for (int r = 0; r < 16; ++r) {
                unsigned short hh, hl;
                split2h(h0v[r], hh, hl);
                Ah[(rb + r) * AS + H0C + u2] = hh;  Al[(rb + r) * AS + H0C + u2] = hl;
                split2h(h1v[r], hh, hl);
                Ah[(rb + r) * AS + H1C + u2] = hh;  Al[(rb + r) * AS + H1C + u2] = hl;
            }
        }
    }
    __syncthreads();

    const uint32_t AhB = smem_u32(Ah);
    const uint32_t AlB = smem_u32(Al);
    const uint32_t pAh = mapa_sh(AhB, cr ^ 1u);
    const uint32_t pAl = mapa_sh(AlB, cr ^ 1u);
    const uint32_t aH = AhB + (lane & 15) * ROWB + (lane >> 4) * 16;
    const uint32_t aL = AlB + (lane & 15) * ROWB + (lane >> 4) * 16;
    const uint4* wf0 = g_W0 + (size_t)slot * KS0 * 128 + lane;
    const uint4* wf1 = g_W1 + (size_t)slot * KS1 * 128 + lane;
    const uint4* wfP = g_PJ + (size_t)wid * 128 + lane;

    cluster_sync_();

    // =============================== time loop ===============================
    for (int t = 0; t < TST; ++t) {
        uint32_t hp[2][8];

        // ---- layer 0 : reads cols 0..287 ----
        #pragma unroll
        for (int half = 0; half < 2; ++half) {
            float acc[2][4][4];
            mma_half<KS0, 128>(aH, aL, wf0 + half * 64, acc);
            lstm_epi(acc, half, odd, c0st, hp);
        }
        cluster_sync_();                              // both CTAs done reading h0_old
        #pragma unroll
        for (int mt = 0; mt < 2; ++mt)
            #pragma unroll
            for (int nt = 0; nt < 8; ++nt) {
                int row = mt * 16 + rbaseA, u = ubase + nt * 2;
                uint32_t off = (uint32_t)(row * AS + H0C + u) * 2;
                unsigned short hh = (unsigned short)hp[mt][nt];
                unsigned short hl = (unsigned short)(hp[mt][nt] >> 16);
                Ah[row * AS + H0C + u] = hh;
                Al[row * AS + H0C + u] = hl;
                st_remote_u16(pAh + off, hh);
                st_remote_u16(pAl + off, hl);
            }
        cluster_sync_();                              // new h0 visible cluster-wide

        // ---- layer 1 : reads cols 16..543 ----
        #pragma unroll
        for (int half = 0; half < 2; ++half) {
            float acc[2][4][4];
            mma_half<KS1, 128>(aH + 32, aL + 32, wf1 + half * 64, acc);
            lstm_epi(acc, half, odd, c1st, hp);
        }
        cluster_sync_();                              // both CTAs done reading h1_old
        #pragma unroll
        for (int mt = 0; mt < 2; ++mt)
            #pragma unroll
            for (int nt = 0; nt < 8; ++nt) {
                int row = mt * 16 + rbaseA, u = ubase + nt * 2;
                uint32_t off = (uint32_t)(row * AS + H1C + u) * 2;
                unsigned short hh = (unsigned short)hp[mt][nt];
                unsigned short hl = (unsigned short)(hp[mt][nt] >> 16);
                Ah[row * AS + H1C + u] = hh;
                Al[row * AS + H1C + u] = hl;
                st_remote_u16(pAh + off, hh);
                st_remote_u16(pAl + off, hl);
            }
        cluster_sync_();                              // new h1 visible cluster-wide

        // ---- projection MMA: 8 warps K-split (K=32 each), partials -> SMEM ----
        {
            float acc[2][4][4];
            mma_half<2, 64>(aH + 2 * H1C + wid * 64, aL + 2 * H1C + wid * 64, wfP, acc);
            #pragma unroll
            for (int mt = 0; mt < 2; ++mt)
                #pragma unroll
                for (int n = 0; n < 4; ++n) {
                    int rr = mt * 16 + (lane >> 2);
                    float* p = pt + wid * 1056 + rr * 33 + n * 8 + tig * 2;
                    p[0]          = acc[mt][n][0];
                    p[1]          = acc[mt][n][1];
                    p[8 * 33]     = acc[mt][n][2];
                    p[8 * 33 + 1] = acc[mt][n][3];
                }
        }
        __syncthreads();

        // ---- reduce partials + bias; rank writes its half of rows to gmem; feed back x ----
        for (int o = tid; o < ROWS * DIM; o += NT) {
            int r = o / DIM, d = o - r * DIM;
            float y = __ldg(b_proj + d);
            #pragma unroll
            for (int w8 = 0; w8 < 8; ++w8) y += pt[w8 * 1056 + r * 33 + d];
            if ((uint32_t)(r >> 4) == cr)
                out[(size_t)(r0 + r) * (TST * DIM) + (size_t)t * DIM + d] = y;
            unsigned short hh, hl;
            split2h(y, hh, hl);
            Ah[r * AS + d] = hh;
            Al[r * AS + d] = hl;
        }
        __syncthreads();
    }
}

extern "C" void kernel_launch(void* const* d_in, const int* in_sizes, int n_in,
                              void* d_out, int out_size) {
    const int wbase = (n_in >= 17) ? 3 : 2;

    const float* z      = (const float*)d_in[0];
    const float* w_lh   = (const float*)d_in[wbase + 0];
    const float* b_lh   = (const float*)d_in[wbase + 1];
    const float* w_lc   = (const float*)d_in[wbase + 2];
    const float* b_lc   = (const float*)d_in[wbase + 3];
    const float* w_ih0  = (const float*)d_in[wbase + 4];
    const float* w_hh0  = (const float*)d_in[wbase + 5];
    const float* b_ih0  = (const float*)d_in[wbase + 6];
    const float* b_hh0  = (const float*)d_in[wbase + 7];
    const float* w_ih1  = (const float*)d_in[wbase + 8];
    const float* w_hh1  = (const float*)d_in[wbase + 9];
    const float* b_ih1  = (const float*)d_in[wbase + 10];
    const float* b_hh1  = (const float*)d_in[wbase + 11];
    const float* w_proj = (const float*)d_in[wbase + 12];
    const float* b_proj = (const float*)d_in[wbase + 13];

    static bool attr_set = false;
    if (!attr_set) {
        cudaFuncSetAttribute(decoder_kernel,
                             cudaFuncAttributeMaxDynamicSharedMemorySize, SMEM_BYTES);
        attr_set = true;
    }

    repack_kernel<<<512, 256>>>(w_ih0, w_hh0, b_ih0, b_hh0,
                                w_ih1, w_hh1, b_ih1, b_hh1, w_proj);
    decoder_kernel<<<NCTA, NT, SMEM_BYTES>>>(z, w_lh, b_lh, w_lc, b_lc,
                                             b_proj, (float*)d_out);
}